// round 4
// baseline (speedup 1.0000x reference)
#include <cuda_runtime.h>
#include <math.h>

#define QD 256    // queries
#define II 2048   // gallery images
#define DD 256    // feature dim

#define BQ 32
#define BI 64
#define KC 16
#define QPITCH 18   // u64 per q-smem row (16 pairs + 2 pad) = 144B, 16B-aligned rows
#define GPITCH 68   // floats per g-smem row = 272B, 16B-aligned rows

typedef unsigned long long u64;

// ---- scratch (__device__ globals; no allocation allowed) ----
__device__ float d_C [QD * DD];   // fqn*A        natural [Q][D]
__device__ float d_A2[QD * DD];   // A^2          natural [Q][D]
__device__ float d_AB[QD * DD];   // 2*A*B        natural [Q][D]
__device__ float d_GT[DD * II];   // normalized gallery, transposed [D][I]
__device__ float d_c0[QD];
__device__ float d_b0;

// ---------------- packed f32x2 helpers ----------------
__device__ __forceinline__ u64 pack2(float lo, float hi) {
    u64 r;
    asm("mov.b64 %0, {%1, %2};" : "=l"(r) : "f"(lo), "f"(hi));
    return r;
}
__device__ __forceinline__ void unpack2(u64 v, float& lo, float& hi) {
    asm("mov.b64 {%0, %1}, %2;" : "=f"(lo), "=f"(hi) : "l"(v));
}
#define FMA2(acc, a, b) \
    asm("fma.rn.f32x2 %0, %1, %2, %0;" : "+l"(acc) : "l"(a), "l"(b))

__device__ __forceinline__ float warpSum(float v) {
    #pragma unroll
    for (int o = 16; o; o >>= 1) v += __shfl_xor_sync(0xffffffffu, v, o);
    return v;
}

// ---------------- fused prep kernel: 64 blocks x 256 threads ----------------
// blocks 0..31  : gallery normalize + transpose (64 rows each)
// blocks 32..63 : query precompute, warp-per-query (8 queries each)
__global__ __launch_bounds__(256) void prep_kernel(
        const float* __restrict__ qf,
        const float* __restrict__ qi,
        const float* __restrict__ gal,
        const float* __restrict__ gamma,
        const float* __restrict__ beta,
        const float* __restrict__ mean,
        const float* __restrict__ var) {
    const int bx  = blockIdx.x;
    const int tid = threadIdx.x;

    if (bx < 32) {
        // ---- gallery part: rows i0..i0+63 ----
        __shared__ float sInv[64];
        __shared__ float sT[32][65];   // transpose staging, conflict-free
        const int i0 = bx * 64;
        const int w = tid >> 5, lane = tid & 31;

        // phase 1: per-row inverse norms
        #pragma unroll
        for (int r = 0; r < 8; r++) {
            int il = w * 8 + r;
            const float4* row = (const float4*)&gal[(i0 + il) * DD];
            float4 a = row[lane];
            float4 b = row[lane + 32];
            float ss = a.x*a.x + a.y*a.y + a.z*a.z + a.w*a.w
                     + b.x*b.x + b.y*b.y + b.z*b.z + b.w*b.w;
            ss = warpSum(ss);
            if (lane == 0) sInv[il] = 1.f / fmaxf(sqrtf(ss), 1e-12f);
        }
        __syncthreads();

        // phase 2: transpose 32-d chunks through smem (all GMEM coalesced)
        for (int dc = 0; dc < DD; dc += 32) {
            #pragma unroll
            for (int it = 0; it < 2; it++) {
                int p  = tid + it * 256;
                int il = p >> 3;       // 0..63
                int kv = p & 7;        // 0..7
                float inv = sInv[il];
                float4 v = *(const float4*)&gal[(i0 + il) * DD + dc + 4 * kv];
                sT[4*kv + 0][il] = v.x * inv;
                sT[4*kv + 1][il] = v.y * inv;
                sT[4*kv + 2][il] = v.z * inv;
                sT[4*kv + 3][il] = v.w * inv;
            }
            __syncthreads();
            #pragma unroll
            for (int half = 0; half < 2; half++) {
                int dl = (tid >> 4) + 16 * half;  // 0..31
                int iv = tid & 15;                // 0..15
                float4 o;
                o.x = sT[dl][4*iv + 0];
                o.y = sT[dl][4*iv + 1];
                o.z = sT[dl][4*iv + 2];
                o.w = sT[dl][4*iv + 3];
                *(float4*)&d_GT[(dc + dl) * II + i0 + 4 * iv] = o;
            }
            __syncthreads();
        }
    } else {
        // ---- query part: warp per query ----
        const int q    = (bx - 32) * 8 + (tid >> 5);
        const int lane = tid & 31;

        float x[8], y[8], istd[8], B[8];
        float xs = 0.f, ys = 0.f;
        #pragma unroll
        for (int j = 0; j < 8; j++) {
            int d = lane + 32 * j;
            x[j] = qf[q * DD + d];
            y[j] = qi[q * DD + d];
            istd[j] = gamma[d] * rsqrtf(var[d] + 1e-5f);
            B[j] = beta[d] - mean[d] * istd[j];
            xs += x[j] * x[j];
            ys += y[j] * y[j];
        }
        xs = warpSum(xs);
        ys = warpSum(ys);
        float xin = 1.f / fmaxf(sqrtf(xs), 1e-12f);
        float yin = 1.f / fmaxf(sqrtf(ys), 1e-12f);

        float A[8], fq[8];
        float fs = 0.f;
        #pragma unroll
        for (int j = 0; j < 8; j++) {
            float xn = x[j] * xin;
            float gate = 1.f / (1.f + __expf(-xn * 5.0f));  // sigmoid(xn/0.2)
            A[j] = gate * istd[j];
            float yn = y[j] * yin;
            fq[j] = yn * A[j] + B[j];
            fs += fq[j] * fq[j];
        }
        fs = warpSum(fs);
        float fin = 1.f / fmaxf(sqrtf(fs), 1e-12f);

        float c0 = 0.f;
        #pragma unroll
        for (int j = 0; j < 8; j++) {
            int d = lane + 32 * j;
            float fqn = fq[j] * fin;
            d_C [q * DD + d] = fqn * A[j];
            d_A2[q * DD + d] = A[j] * A[j];
            d_AB[q * DD + d] = 2.f * A[j] * B[j];
            c0 += fqn * B[j];
        }
        c0 = warpSum(c0);
        if (lane == 0) d_c0[q] = c0;

        if (q == 0) {
            float b0 = 0.f;
            #pragma unroll
            for (int j = 0; j < 8; j++) b0 += B[j] * B[j];
            b0 = warpSum(b0);
            if (lane == 0) d_b0 = b0;
        }
    }
}

// ---------------- main scoring kernel ----------------
// grid (II/BI, QD/BQ) = (32, 8) = 256 blocks, block 256 threads
// micro-tile: 2 q x 4 i per thread; kc processed in pairs (LDS.128 on q side)
__global__ __launch_bounds__(256) void score_kernel(float* __restrict__ out) {
    __shared__ u64  sC [BQ][QPITCH];   // pre-duplicated f32x2 pairs [q][kc]
    __shared__ u64  sA2[BQ][QPITCH];
    __shared__ u64  sAB[BQ][QPITCH];
    __shared__ float sG [KC][GPITCH];  // [kc][i]
    __shared__ float sG2[KC][GPITCH];  // g^2

    const int tid = threadIdx.x;
    const int tx = tid & 15;   // i direction: 4 floats = 2 pairs
    const int ty = tid >> 4;   // q direction: rows 2*ty, 2*ty+1
    const int i0 = blockIdx.x * BI;
    const int q0 = blockIdx.y * BQ;

    u64 s1[2][2], s2[2][2];
    #pragma unroll
    for (int u = 0; u < 2; u++) {
        s1[u][0] = 0ull; s1[u][1] = 0ull;
        s2[u][0] = 0ull; s2[u][1] = 0ull;
    }

    const int lq  = tid >> 2;  // 0..63 (only tid<128 -> 0..31 used)
    const int lkv = tid & 3;   // 0..3
    const int gkc = tid >> 4;  // 0..15
    const int giv = tid & 15;  // 0..15

    for (int k0 = 0; k0 < DD; k0 += KC) {
        __syncthreads();
        if (tid < 128) {
            float4 c  = *(const float4*)&d_C [(q0 + lq) * DD + k0 + 4 * lkv];
            float4 a2 = *(const float4*)&d_A2[(q0 + lq) * DD + k0 + 4 * lkv];
            float4 ab = *(const float4*)&d_AB[(q0 + lq) * DD + k0 + 4 * lkv];
            u64* pc = &sC [lq][4 * lkv];
            u64* pa = &sA2[lq][4 * lkv];
            u64* pb = &sAB[lq][4 * lkv];
            pc[0] = pack2(c.x,  c.x);  pc[1] = pack2(c.y,  c.y);
            pc[2] = pack2(c.z,  c.z);  pc[3] = pack2(c.w,  c.w);
            pa[0] = pack2(a2.x, a2.x); pa[1] = pack2(a2.y, a2.y);
            pa[2] = pack2(a2.z, a2.z); pa[3] = pack2(a2.w, a2.w);
            pb[0] = pack2(ab.x, ab.x); pb[1] = pack2(ab.y, ab.y);
            pb[2] = pack2(ab.z, ab.z); pb[3] = pack2(ab.w, ab.w);
        }
        {
            float4 g = *(const float4*)&d_GT[(k0 + gkc) * II + i0 + 4 * giv];
            *(float4*)&sG[gkc][4 * giv] = g;
            float4 g2;
            g2.x = g.x * g.x; g2.y = g.y * g.y;
            g2.z = g.z * g.z; g2.w = g.w * g.w;
            *(float4*)&sG2[gkc][4 * giv] = g2;
        }
        __syncthreads();

        const u64* pC0  = &sC [ty * 2][0];
        const u64* pA20 = &sA2[ty * 2][0];
        const u64* pAB0 = &sAB[ty * 2][0];

        #pragma unroll
        for (int kc = 0; kc < KC; kc += 2) {
            ulonglong2 gv0  = *(const ulonglong2*)&sG [kc    ][tx * 4];
            ulonglong2 g2v0 = *(const ulonglong2*)&sG2[kc    ][tx * 4];
            ulonglong2 gv1  = *(const ulonglong2*)&sG [kc + 1][tx * 4];
            ulonglong2 g2v1 = *(const ulonglong2*)&sG2[kc + 1][tx * 4];
            #pragma unroll
            for (int u = 0; u < 2; u++) {
                ulonglong2 cp  = *(const ulonglong2*)(pC0  + u * QPITCH + kc);
                ulonglong2 ap  = *(const ulonglong2*)(pA20 + u * QPITCH + kc);
                ulonglong2 bp  = *(const ulonglong2*)(pAB0 + u * QPITCH + kc);
                FMA2(s1[u][0], cp.x, gv0.x);
                FMA2(s1[u][1], cp.x, gv0.y);
                FMA2(s2[u][0], ap.x, g2v0.x);
                FMA2(s2[u][1], ap.x, g2v0.y);
                FMA2(s2[u][0], bp.x, gv0.x);
                FMA2(s2[u][1], bp.x, gv0.y);
                FMA2(s1[u][0], cp.y, gv1.x);
                FMA2(s1[u][1], cp.y, gv1.y);
                FMA2(s2[u][0], ap.y, g2v1.x);
                FMA2(s2[u][1], ap.y, g2v1.y);
                FMA2(s2[u][0], bp.y, gv1.x);
                FMA2(s2[u][1], bp.y, gv1.y);
            }
        }
    }

    // epilogue: score = sigmoid((s1+c0) / max(sqrt(s2+b0), 1e-12))
    const float b0 = d_b0;
    #pragma unroll
    for (int u = 0; u < 2; u++) {
        int q = q0 + ty * 2 + u;
        float c0 = d_c0[q];
        float a[4], b[4];
        unpack2(s1[u][0], a[0], a[1]);
        unpack2(s1[u][1], a[2], a[3]);
        unpack2(s2[u][0], b[0], b[1]);
        unpack2(s2[u][1], b[2], b[3]);
        float4 r;
        float* rp = &r.x;
        #pragma unroll
        for (int v = 0; v < 4; v++) {
            float denom = fmaxf(sqrtf(b[v] + b0), 1e-12f);
            float val = (a[v] + c0) / denom;
            rp[v] = 1.f / (1.f + __expf(-val));
        }
        *(float4*)&out[q * II + i0 + tx * 4] = r;
    }
}

extern "C" void kernel_launch(void* const* d_in, const int* in_sizes, int n_in,
                              void* d_out, int out_size) {
    const float* query_feats       = (const float*)d_in[0];
    const float* query_img_feats   = (const float*)d_in[1];
    const float* gallery_img_feats = (const float*)d_in[2];
    const float* bn_gamma          = (const float*)d_in[3];
    const float* bn_beta           = (const float*)d_in[4];
    const float* bn_mean           = (const float*)d_in[5];
    const float* bn_var            = (const float*)d_in[6];
    float* out = (float*)d_out;

    prep_kernel<<<64, 256>>>(query_feats, query_img_feats, gallery_img_feats,
                             bn_gamma, bn_beta, bn_mean, bn_var);
    dim3 grid(II / BI, QD / BQ);
    score_kernel<<<grid, 256>>>(out);
}

// round 5
// speedup vs baseline: 1.1875x; 1.1875x over previous
#include <cuda_runtime.h>
#include <math.h>

#define QD 256    // queries
#define II 2048   // gallery images
#define DD 256    // feature dim

#define BQ 32
#define BI 128
#define KC 16
#define NT (DD / KC)   // 16 k-tiles
#define QP 18          // u64 pitch for q-coeff rows: 144B, 16B-aligned, kc-even -> aligned LDS.128

typedef unsigned long long u64;

// ---- scratch (__device__ globals; no allocation allowed) ----
__device__ float d_C [QD * DD];   // fqn*A   natural [Q][D]
__device__ float d_A2[QD * DD];   // A^2     natural [Q][D]
__device__ float d_AB[QD * DD];   // 2*A*B   natural [Q][D]
__device__ float d_GT[DD * II];   // normalized gallery, transposed [D][I]
__device__ float d_c0[QD];
__device__ float d_b0;

// ---------------- packed f32x2 helpers ----------------
__device__ __forceinline__ u64 pack2(float lo, float hi) {
    u64 r;
    asm("mov.b64 %0, {%1, %2};" : "=l"(r) : "f"(lo), "f"(hi));
    return r;
}
__device__ __forceinline__ void unpack2(u64 v, float& lo, float& hi) {
    asm("mov.b64 {%0, %1}, %2;" : "=f"(lo), "=f"(hi) : "l"(v));
}
// acc += a*b
#define FMA2(acc, a, b) \
    asm("fma.rn.f32x2 %0, %1, %2, %0;" : "+l"(acc) : "l"(a), "l"(b))
// d = a*b + c
#define FMA2R(d, a, b, c) \
    asm("fma.rn.f32x2 %0, %1, %2, %3;" : "=l"(d) : "l"(a), "l"(b), "l"(c))

__device__ __forceinline__ float warpSum(float v) {
    #pragma unroll
    for (int o = 16; o; o >>= 1) v += __shfl_xor_sync(0xffffffffu, v, o);
    return v;
}

// ---------------- fused prep kernel: 64 blocks x 256 threads ----------------
__global__ __launch_bounds__(256) void prep_kernel(
        const float* __restrict__ qf,
        const float* __restrict__ qi,
        const float* __restrict__ gal,
        const float* __restrict__ gamma,
        const float* __restrict__ beta,
        const float* __restrict__ mean,
        const float* __restrict__ var) {
    const int bx  = blockIdx.x;
    const int tid = threadIdx.x;

    if (bx < 32) {
        // ---- gallery part: normalize + transpose rows i0..i0+63 ----
        __shared__ float sInv[64];
        __shared__ float sT[32][65];
        const int i0 = bx * 64;
        const int w = tid >> 5, lane = tid & 31;

        #pragma unroll
        for (int r = 0; r < 8; r++) {
            int il = w * 8 + r;
            const float4* row = (const float4*)&gal[(i0 + il) * DD];
            float4 a = row[lane];
            float4 b = row[lane + 32];
            float ss = a.x*a.x + a.y*a.y + a.z*a.z + a.w*a.w
                     + b.x*b.x + b.y*b.y + b.z*b.z + b.w*b.w;
            ss = warpSum(ss);
            if (lane == 0) sInv[il] = 1.f / fmaxf(sqrtf(ss), 1e-12f);
        }
        __syncthreads();

        for (int dc = 0; dc < DD; dc += 32) {
            #pragma unroll
            for (int it = 0; it < 2; it++) {
                int p  = tid + it * 256;
                int il = p >> 3;
                int kv = p & 7;
                float inv = sInv[il];
                float4 v = *(const float4*)&gal[(i0 + il) * DD + dc + 4 * kv];
                sT[4*kv + 0][il] = v.x * inv;
                sT[4*kv + 1][il] = v.y * inv;
                sT[4*kv + 2][il] = v.z * inv;
                sT[4*kv + 3][il] = v.w * inv;
            }
            __syncthreads();
            #pragma unroll
            for (int half = 0; half < 2; half++) {
                int dl = (tid >> 4) + 16 * half;
                int iv = tid & 15;
                float4 o;
                o.x = sT[dl][4*iv + 0];
                o.y = sT[dl][4*iv + 1];
                o.z = sT[dl][4*iv + 2];
                o.w = sT[dl][4*iv + 3];
                *(float4*)&d_GT[(dc + dl) * II + i0 + 4 * iv] = o;
            }
            __syncthreads();
        }
    } else {
        // ---- query part: warp per query ----
        const int q    = (bx - 32) * 8 + (tid >> 5);
        const int lane = tid & 31;

        float x[8], y[8], istd[8], B[8];
        float xs = 0.f, ys = 0.f;
        #pragma unroll
        for (int j = 0; j < 8; j++) {
            int d = lane + 32 * j;
            x[j] = qf[q * DD + d];
            y[j] = qi[q * DD + d];
            istd[j] = gamma[d] * rsqrtf(var[d] + 1e-5f);
            B[j] = beta[d] - mean[d] * istd[j];
            xs += x[j] * x[j];
            ys += y[j] * y[j];
        }
        xs = warpSum(xs);
        ys = warpSum(ys);
        float xin = 1.f / fmaxf(sqrtf(xs), 1e-12f);
        float yin = 1.f / fmaxf(sqrtf(ys), 1e-12f);

        float A[8], fq[8];
        float fs = 0.f;
        #pragma unroll
        for (int j = 0; j < 8; j++) {
            float xn = x[j] * xin;
            float gate = 1.f / (1.f + __expf(-xn * 5.0f));  // sigmoid(xn/0.2)
            A[j] = gate * istd[j];
            float yn = y[j] * yin;
            fq[j] = yn * A[j] + B[j];
            fs += fq[j] * fq[j];
        }
        fs = warpSum(fs);
        float fin = 1.f / fmaxf(sqrtf(fs), 1e-12f);

        float c0 = 0.f;
        #pragma unroll
        for (int j = 0; j < 8; j++) {
            int d = lane + 32 * j;
            float fqn = fq[j] * fin;
            d_C [q * DD + d] = fqn * A[j];
            d_A2[q * DD + d] = A[j] * A[j];
            d_AB[q * DD + d] = 2.f * A[j] * B[j];
            c0 += fqn * B[j];
        }
        c0 = warpSum(c0);
        if (lane == 0) d_c0[q] = c0;

        if (q == 0) {
            float b0 = 0.f;
            #pragma unroll
            for (int j = 0; j < 8; j++) b0 += B[j] * B[j];
            b0 = warpSum(b0);
            if (lane == 0) d_b0 = b0;
        }
    }
}

// ---------------- main scoring kernel ----------------
// grid (II/BI, QD/BQ) = (16, 8) = 128 blocks; 256 threads = 8 warps
// warp w owns q rows q0+4w..+3 (warp-uniform q -> coeff LDS are broadcasts);
// lane spans i: 4 floats each, 128 i per warp.
__global__ __launch_bounds__(256) void score_kernel(float* __restrict__ out) {
    __shared__ float sG[2][KC][BI];       // 16 KB
    __shared__ u64   sC [2][BQ][QP];      // duplicated f32x2 pairs
    __shared__ u64   sA2[2][BQ][QP];
    __shared__ u64   sAB[2][BQ][QP];

    const int tid  = threadIdx.x;
    const int warp = tid >> 5;
    const int lane = tid & 31;
    const int i0 = blockIdx.x * BI;
    const int q0 = blockIdx.y * BQ;

    u64 s1[4][2], s2[4][2];
    #pragma unroll
    for (int u = 0; u < 4; u++) {
        s1[u][0] = 0ull; s1[u][1] = 0ull;
        s2[u][0] = 0ull; s2[u][1] = 0ull;
    }

    // q-coeff loader mapping (first 128 threads): lq 0..31, lkv 0..3
    const int lq  = tid >> 2;
    const int lkv = tid & 3;

    // prefetch registers
    float4 pg0, pg1, pc, pa, pb;

    auto ldg_tile = [&](int t) {
        const int k0 = t * KC;
        pg0 = *(const float4*)&d_GT[(k0 + warp    ) * II + i0 + 4 * lane];
        pg1 = *(const float4*)&d_GT[(k0 + warp + 8) * II + i0 + 4 * lane];
        if (tid < 128) {
            pc = *(const float4*)&d_C [(q0 + lq) * DD + k0 + 4 * lkv];
            pa = *(const float4*)&d_A2[(q0 + lq) * DD + k0 + 4 * lkv];
            pb = *(const float4*)&d_AB[(q0 + lq) * DD + k0 + 4 * lkv];
        }
    };
    auto sts_tile = [&](int buf) {
        *(float4*)&sG[buf][warp    ][4 * lane] = pg0;
        *(float4*)&sG[buf][warp + 8][4 * lane] = pg1;
        if (tid < 128) {
            u64* c = &sC [buf][lq][4 * lkv];
            u64* a = &sA2[buf][lq][4 * lkv];
            u64* b = &sAB[buf][lq][4 * lkv];
            c[0] = pack2(pc.x, pc.x); c[1] = pack2(pc.y, pc.y);
            c[2] = pack2(pc.z, pc.z); c[3] = pack2(pc.w, pc.w);
            a[0] = pack2(pa.x, pa.x); a[1] = pack2(pa.y, pa.y);
            a[2] = pack2(pa.z, pa.z); a[3] = pack2(pa.w, pa.w);
            b[0] = pack2(pb.x, pb.x); b[1] = pack2(pb.y, pb.y);
            b[2] = pack2(pb.z, pb.z); b[3] = pack2(pb.w, pb.w);
        }
    };

    ldg_tile(0);
    sts_tile(0);
    __syncthreads();

    for (int t = 0; t < NT; t++) {
        const int buf = t & 1;
        if (t + 1 < NT) ldg_tile(t + 1);

        const u64* pC  = &sC [buf][warp * 4][0];
        const u64* pA2 = &sA2[buf][warp * 4][0];
        const u64* pAB = &sAB[buf][warp * 4][0];

        #pragma unroll
        for (int kc = 0; kc < KC; kc += 2) {
            ulonglong2 g0 = *(const ulonglong2*)&sG[buf][kc    ][4 * lane];
            ulonglong2 g1 = *(const ulonglong2*)&sG[buf][kc + 1][4 * lane];
            #pragma unroll
            for (int u = 0; u < 4; u++) {
                ulonglong2 cp = *(const ulonglong2*)(pC  + u * QP + kc);
                ulonglong2 ap = *(const ulonglong2*)(pA2 + u * QP + kc);
                ulonglong2 bp = *(const ulonglong2*)(pAB + u * QP + kc);
                u64 t00, t01, t10, t11;
                // kc
                FMA2(s1[u][0], cp.x, g0.x);
                FMA2(s1[u][1], cp.x, g0.y);
                FMA2R(t00, ap.x, g0.x, bp.x);
                FMA2R(t01, ap.x, g0.y, bp.x);
                FMA2(s2[u][0], t00, g0.x);
                FMA2(s2[u][1], t01, g0.y);
                // kc+1
                FMA2(s1[u][0], cp.y, g1.x);
                FMA2(s1[u][1], cp.y, g1.y);
                FMA2R(t10, ap.y, g1.x, bp.y);
                FMA2R(t11, ap.y, g1.y, bp.y);
                FMA2(s2[u][0], t10, g1.x);
                FMA2(s2[u][1], t11, g1.y);
            }
        }

        if (t + 1 < NT) sts_tile((t + 1) & 1);
        __syncthreads();
    }

    // epilogue: score = sigmoid((s1+c0) / max(sqrt(s2+b0), 1e-12))
    const float b0 = d_b0;
    #pragma unroll
    for (int u = 0; u < 4; u++) {
        int q = q0 + warp * 4 + u;
        float c0 = d_c0[q];
        float a[4], b[4];
        unpack2(s1[u][0], a[0], a[1]);
        unpack2(s1[u][1], a[2], a[3]);
        unpack2(s2[u][0], b[0], b[1]);
        unpack2(s2[u][1], b[2], b[3]);
        float4 r;
        float* rp = &r.x;
        #pragma unroll
        for (int v = 0; v < 4; v++) {
            float denom = fmaxf(sqrtf(b[v] + b0), 1e-12f);
            float val = (a[v] + c0) / denom;
            rp[v] = 1.f / (1.f + __expf(-val));
        }
        *(float4*)&out[q * II + i0 + 4 * lane] = r;
    }
}

extern "C" void kernel_launch(void* const* d_in, const int* in_sizes, int n_in,
                              void* d_out, int out_size) {
    const float* query_feats       = (const float*)d_in[0];
    const float* query_img_feats   = (const float*)d_in[1];
    const float* gallery_img_feats = (const float*)d_in[2];
    const float* bn_gamma          = (const float*)d_in[3];
    const float* bn_beta           = (const float*)d_in[4];
    const float* bn_mean           = (const float*)d_in[5];
    const float* bn_var            = (const float*)d_in[6];
    float* out = (float*)d_out;

    prep_kernel<<<64, 256>>>(query_feats, query_img_feats, gallery_img_feats,
                             bn_gamma, bn_beta, bn_mean, bn_var);
    dim3 grid(II / BI, QD / BQ);
    score_kernel<<<grid, 256>>>(out);
}

// round 7
// speedup vs baseline: 1.3745x; 1.1574x over previous
#include <cuda_runtime.h>
#include <math.h>

#define QD 256    // queries
#define II 2048   // gallery images
#define DD 256    // feature dim

#define BQ 32
#define BI 128
#define KC 16
#define NTS 8          // tiles per k-group (128 / 16)
#define QP 18          // u64 pitch for q-coeff rows (144B, 16B-aligned)

typedef unsigned long long u64;

// ---- scratch (__device__ globals; no allocation allowed) ----
__device__ float d_C [QD * DD];   // fqn*A   natural [Q][D]
__device__ float d_A2[QD * DD];   // A^2     natural [Q][D]
__device__ float d_AB[QD * DD];   // 2*A*B   natural [Q][D]
__device__ float d_GT[DD * II];   // normalized gallery, transposed [D][I]
__device__ float d_c0[QD];
__device__ float d_b0;

// ---------------- packed f32x2 helpers ----------------
__device__ __forceinline__ u64 pack2(float lo, float hi) {
    u64 r;
    asm("mov.b64 %0, {%1, %2};" : "=l"(r) : "f"(lo), "f"(hi));
    return r;
}
__device__ __forceinline__ void unpack2(u64 v, float& lo, float& hi) {
    asm("mov.b64 {%0, %1}, %2;" : "=f"(lo), "=f"(hi) : "l"(v));
}
#define FMA2(acc, a, b) \
    asm("fma.rn.f32x2 %0, %1, %2, %0;" : "+l"(acc) : "l"(a), "l"(b))
#define FMA2R(d, a, b, c) \
    asm("fma.rn.f32x2 %0, %1, %2, %3;" : "=l"(d) : "l"(a), "l"(b), "l"(c))
#define ADD2(acc, v) \
    asm("add.rn.f32x2 %0, %0, %1;" : "+l"(acc) : "l"(v))

__device__ __forceinline__ float warpSum(float v) {
    #pragma unroll
    for (int o = 16; o; o >>= 1) v += __shfl_xor_sync(0xffffffffu, v, o);
    return v;
}

// ---------------- fused prep kernel: 64 blocks x 256 threads ----------------
__global__ __launch_bounds__(256) void prep_kernel(
        const float* __restrict__ qf,
        const float* __restrict__ qi,
        const float* __restrict__ gal,
        const float* __restrict__ gamma,
        const float* __restrict__ beta,
        const float* __restrict__ mean,
        const float* __restrict__ var) {
    const int bx  = blockIdx.x;
    const int tid = threadIdx.x;

    if (bx < 32) {
        // ---- gallery part: normalize + transpose rows i0..i0+63 ----
        __shared__ float sInv[64];
        __shared__ float sT[32][65];
        const int i0 = bx * 64;
        const int w = tid >> 5, lane = tid & 31;

        #pragma unroll
        for (int r = 0; r < 8; r++) {
            int il = w * 8 + r;
            const float4* row = (const float4*)&gal[(i0 + il) * DD];
            float4 a = row[lane];
            float4 b = row[lane + 32];
            float ss = a.x*a.x + a.y*a.y + a.z*a.z + a.w*a.w
                     + b.x*b.x + b.y*b.y + b.z*b.z + b.w*b.w;
            ss = warpSum(ss);
            if (lane == 0) sInv[il] = 1.f / fmaxf(sqrtf(ss), 1e-12f);
        }
        __syncthreads();

        for (int dc = 0; dc < DD; dc += 32) {
            #pragma unroll
            for (int it = 0; it < 2; it++) {
                int p  = tid + it * 256;
                int il = p >> 3;
                int kv = p & 7;
                float inv = sInv[il];
                float4 v = *(const float4*)&gal[(i0 + il) * DD + dc + 4 * kv];
                sT[4*kv + 0][il] = v.x * inv;
                sT[4*kv + 1][il] = v.y * inv;
                sT[4*kv + 2][il] = v.z * inv;
                sT[4*kv + 3][il] = v.w * inv;
            }
            __syncthreads();
            #pragma unroll
            for (int half = 0; half < 2; half++) {
                int dl = (tid >> 4) + 16 * half;
                int iv = tid & 15;
                float4 o;
                o.x = sT[dl][4*iv + 0];
                o.y = sT[dl][4*iv + 1];
                o.z = sT[dl][4*iv + 2];
                o.w = sT[dl][4*iv + 3];
                *(float4*)&d_GT[(dc + dl) * II + i0 + 4 * iv] = o;
            }
            __syncthreads();
        }
    } else {
        // ---- query part: warp per query ----
        const int q    = (bx - 32) * 8 + (tid >> 5);
        const int lane = tid & 31;

        float x[8], y[8], istd[8], B[8];
        float xs = 0.f, ys = 0.f;
        #pragma unroll
        for (int j = 0; j < 8; j++) {
            int d = lane + 32 * j;
            x[j] = qf[q * DD + d];
            y[j] = qi[q * DD + d];
            istd[j] = gamma[d] * rsqrtf(var[d] + 1e-5f);
            B[j] = beta[d] - mean[d] * istd[j];
            xs += x[j] * x[j];
            ys += y[j] * y[j];
        }
        xs = warpSum(xs);
        ys = warpSum(ys);
        float xin = 1.f / fmaxf(sqrtf(xs), 1e-12f);
        float yin = 1.f / fmaxf(sqrtf(ys), 1e-12f);

        float A[8], fq[8];
        float fs = 0.f;
        #pragma unroll
        for (int j = 0; j < 8; j++) {
            float xn = x[j] * xin;
            float gate = 1.f / (1.f + __expf(-xn * 5.0f));  // sigmoid(xn/0.2)
            A[j] = gate * istd[j];
            float yn = y[j] * yin;
            fq[j] = yn * A[j] + B[j];
            fs += fq[j] * fq[j];
        }
        fs = warpSum(fs);
        float fin = 1.f / fmaxf(sqrtf(fs), 1e-12f);

        float c0 = 0.f;
        #pragma unroll
        for (int j = 0; j < 8; j++) {
            int d = lane + 32 * j;
            float fqn = fq[j] * fin;
            d_C [q * DD + d] = fqn * A[j];
            d_A2[q * DD + d] = A[j] * A[j];
            d_AB[q * DD + d] = 2.f * A[j] * B[j];
            c0 += fqn * B[j];
        }
        c0 = warpSum(c0);
        if (lane == 0) d_c0[q] = c0;

        if (q == 0) {
            float b0 = 0.f;
            #pragma unroll
            for (int j = 0; j < 8; j++) b0 += B[j] * B[j];
            b0 = warpSum(b0);
            if (lane == 0) d_b0 = b0;
        }
    }
}

// ---------------- main scoring kernel ----------------
// grid (16, 8) = 128 blocks; 512 threads = 16 warps.
// k-split: warps 0-7 (group 0) accumulate k in [0,128), warps 8-15 (group 1)
// accumulate k in [128,256), over the same 32q x 128i tile. Per-group smem.
// Warp wg owns q rows q0+4wg..+3 (coeff LDS = broadcasts); lane spans 4 i.
// Final cross-group reduction of accumulators through smem.

#define SG_OFF   0                                  // [2][KC][BI] floats: 16 KB
#define SC_OFF   (2 * KC * BI * 4)                  // [2][BQ][QP] u64: 9216 B
#define SA2_OFF  (SC_OFF  + 2 * BQ * QP * 8)
#define SAB_OFF  (SA2_OFF + 2 * BQ * QP * 8)
#define SMEM_SZ  (SAB_OFF + 2 * BQ * QP * 8)        // 43648 B < 48 KB

__global__ __launch_bounds__(512) void score_kernel(float* __restrict__ out) {
    __shared__ __align__(16) char smem_raw[SMEM_SZ];
    float (*sG)[KC][BI]  = (float (*)[KC][BI])(smem_raw + SG_OFF);
    u64   (*sC)[BQ][QP]  = (u64 (*)[BQ][QP])(smem_raw + SC_OFF);
    u64   (*sA2)[BQ][QP] = (u64 (*)[BQ][QP])(smem_raw + SA2_OFF);
    u64   (*sAB)[BQ][QP] = (u64 (*)[BQ][QP])(smem_raw + SAB_OFF);

    const int tid  = threadIdx.x;
    const int warp = tid >> 5;
    const int lane = tid & 31;
    const int gsel = warp >> 3;   // 0 or 1 (k-group)
    const int wg   = warp & 7;    // warp within group
    const int gt   = tid & 255;   // thread within group
    const int i0 = blockIdx.x * BI;
    const int q0 = blockIdx.y * BQ;
    const int kbase = gsel * 128;

    u64 s1[4][2], s2[4][2];
    #pragma unroll
    for (int u = 0; u < 4; u++) {
        s1[u][0] = 0ull; s1[u][1] = 0ull;
        s2[u][0] = 0ull; s2[u][1] = 0ull;
    }

    // loader mappings (within group)
    const int gkc = gt >> 4;   // 0..15 : kc row for g
    const int giv = gt & 15;   // 0..15 : float4 slot; covers i via two halves
    const int lq  = gt >> 2;   // (only gt<128) 0..31
    const int lkv = gt & 3;    // 0..3

    float4 pgA, pgB, pc, pa, pb;

    auto ldg_tile = [&](int t) {
        const int k0 = kbase + t * KC;
        const float* grow = &d_GT[(k0 + gkc) * II + i0];
        pgA = *(const float4*)&grow[4 * giv];        // i  0..63
        pgB = *(const float4*)&grow[64 + 4 * giv];   // i 64..127
        if (gt < 128) {
            pc = *(const float4*)&d_C [(q0 + lq) * DD + k0 + 4 * lkv];
            pa = *(const float4*)&d_A2[(q0 + lq) * DD + k0 + 4 * lkv];
            pb = *(const float4*)&d_AB[(q0 + lq) * DD + k0 + 4 * lkv];
        }
    };
    auto sts_tile = [&]() {
        *(float4*)&sG[gsel][gkc][4 * giv]      = pgA;
        *(float4*)&sG[gsel][gkc][64 + 4 * giv] = pgB;
        if (gt < 128) {
            u64* c = &sC [gsel][lq][4 * lkv];
            u64* a = &sA2[gsel][lq][4 * lkv];
            u64* b = &sAB[gsel][lq][4 * lkv];
            c[0] = pack2(pc.x, pc.x); c[1] = pack2(pc.y, pc.y);
            c[2] = pack2(pc.z, pc.z); c[3] = pack2(pc.w, pc.w);
            a[0] = pack2(pa.x, pa.x); a[1] = pack2(pa.y, pa.y);
            a[2] = pack2(pa.z, pa.z); a[3] = pack2(pa.w, pa.w);
            b[0] = pack2(pb.x, pb.x); b[1] = pack2(pb.y, pb.y);
            b[2] = pack2(pb.z, pb.z); b[3] = pack2(pb.w, pb.w);
        }
    };

    ldg_tile(0);
    sts_tile();
    __syncthreads();

    for (int t = 0; t < NTS; t++) {
        if (t + 1 < NTS) ldg_tile(t + 1);

        const u64* pC  = &sC [gsel][wg * 4][0];
        const u64* pA2 = &sA2[gsel][wg * 4][0];
        const u64* pAB = &sAB[gsel][wg * 4][0];

        #pragma unroll
        for (int kc = 0; kc < KC; kc += 2) {
            ulonglong2 g0 = *(const ulonglong2*)&sG[gsel][kc    ][4 * lane];
            ulonglong2 g1 = *(const ulonglong2*)&sG[gsel][kc + 1][4 * lane];
            #pragma unroll
            for (int u = 0; u < 4; u++) {
                ulonglong2 cp = *(const ulonglong2*)(pC  + u * QP + kc);
                ulonglong2 ap = *(const ulonglong2*)(pA2 + u * QP + kc);
                ulonglong2 bp = *(const ulonglong2*)(pAB + u * QP + kc);
                u64 t00, t01, t10, t11;
                FMA2(s1[u][0], cp.x, g0.x);
                FMA2(s1[u][1], cp.x, g0.y);
                FMA2R(t00, ap.x, g0.x, bp.x);
                FMA2R(t01, ap.x, g0.y, bp.x);
                FMA2(s2[u][0], t00, g0.x);
                FMA2(s2[u][1], t01, g0.y);
                FMA2(s1[u][0], cp.y, g1.x);
                FMA2(s1[u][1], cp.y, g1.y);
                FMA2R(t10, ap.y, g1.x, bp.y);
                FMA2R(t11, ap.y, g1.y, bp.y);
                FMA2(s2[u][0], t10, g1.x);
                FMA2(s2[u][1], t11, g1.y);
            }
        }

        __syncthreads();          // all warps done reading tile t
        if (t + 1 < NTS) {
            sts_tile();
            __syncthreads();
        }
    }

    // ---- cross-group reduction (group 1 -> group 0) through smem ----
    ulonglong2* red = (ulonglong2*)smem_raw;  // 256 thr * 8 pairs = 32 KB
    if (gsel == 1) {
        #pragma unroll
        for (int u = 0; u < 4; u++) {
            ulonglong2 v1; v1.x = s1[u][0]; v1.y = s1[u][1];
            ulonglong2 v2; v2.x = s2[u][0]; v2.y = s2[u][1];
            red[u * 256 + wg * 32 + lane]       = v1;
            red[(4 + u) * 256 + wg * 32 + lane] = v2;
        }
    }
    __syncthreads();
    if (gsel == 0) {
        #pragma unroll
        for (int u = 0; u < 4; u++) {
            ulonglong2 v1 = red[u * 256 + wg * 32 + lane];
            ulonglong2 v2 = red[(4 + u) * 256 + wg * 32 + lane];
            ADD2(s1[u][0], v1.x); ADD2(s1[u][1], v1.y);
            ADD2(s2[u][0], v2.x); ADD2(s2[u][1], v2.y);
        }

        // epilogue: score = sigmoid((s1+c0) / max(sqrt(s2+b0), 1e-12))
        const float b0 = d_b0;
        #pragma unroll
        for (int u = 0; u < 4; u++) {
            int q = q0 + wg * 4 + u;
            float c0 = d_c0[q];
            float a[4], b[4];
            unpack2(s1[u][0], a[0], a[1]);
            unpack2(s1[u][1], a[2], a[3]);
            unpack2(s2[u][0], b[0], b[1]);
            unpack2(s2[u][1], b[2], b[3]);
            float4 r;
            float* rp = &r.x;
            #pragma unroll
            for (int v = 0; v < 4; v++) {
                float denom = fmaxf(sqrtf(b[v] + b0), 1e-12f);
                float val = (a[v] + c0) / denom;
                rp[v] = 1.f / (1.f + __expf(-val));
            }
            *(float4*)&out[q * II + i0 + 4 * lane] = r;
        }
    }
}

extern "C" void kernel_launch(void* const* d_in, const int* in_sizes, int n_in,
                              void* d_out, int out_size) {
    const float* query_feats       = (const float*)d_in[0];
    const float* query_img_feats   = (const float*)d_in[1];
    const float* gallery_img_feats = (const float*)d_in[2];
    const float* bn_gamma          = (const float*)d_in[3];
    const float* bn_beta           = (const float*)d_in[4];
    const float* bn_mean           = (const float*)d_in[5];
    const float* bn_var            = (const float*)d_in[6];
    float* out = (float*)d_out;

    prep_kernel<<<64, 256>>>(query_feats, query_img_feats, gallery_img_feats,
                             bn_gamma, bn_beta, bn_mean, bn_var);
    dim3 grid(II / BI, QD / BQ);
    score_kernel<<<grid, 512>>>(out);
}